// round 15
// baseline (speedup 1.0000x reference)
#include <cuda_runtime.h>
#include <cuda_fp16.h>
#include <cstdint>

// Problem constants
#define TN      2000
#define UN      50000
#define TF      16
#define NOUT    52          // 16 static + 36 emb
#define UN_PAD  50048       // 782 * 64
#define KTILES  782
#define KSPLIT  18          // 16 mtiles * 18 = 288 CTAs = one wave at occ 2
#define MT      128
#define MTILES  16          // 2048 / 128

// Device scratch (no allocations allowed)
__device__ __half g_ubT[64 * UN_PAD];   // U_emb^T fp16: rows 0..35 emb, 36 ones, 37..39 zero pad
__device__ float g_partial[(size_t)2048 * KSPLIT * 40];   // [gm][ks][40]
__device__ int g_ks_count[KSPLIT];      // per-ks prep barrier (sense-reversal)
__device__ int g_ks_sense[KSPLIT];
__device__ int g_m_count[MTILES];       // per-mtile finalize ticket (last-arriver)

__device__ __forceinline__ uint32_t sw128(uint32_t off) {
    return off ^ ((off >> 3) & 0x70u);
}
__device__ __forceinline__ uint32_t cvta_sh(const void* p) {
    return (uint32_t)__cvta_generic_to_shared(p);
}
__device__ __forceinline__ void ldsm_x4(uint32_t* r, uint32_t addr) {
    asm volatile("ldmatrix.sync.aligned.m8n8.x4.shared.b16 {%0,%1,%2,%3}, [%4];"
                 : "=r"(r[0]), "=r"(r[1]), "=r"(r[2]), "=r"(r[3]) : "r"(addr));
}
__device__ __forceinline__ void mma16816(float* c, const uint32_t* a, uint32_t b0, uint32_t b1) {
    asm volatile(
        "mma.sync.aligned.m16n8k16.row.col.f32.f16.f16.f32 "
        "{%0,%1,%2,%3}, {%4,%5,%6,%7}, {%8,%9}, {%0,%1,%2,%3};"
        : "+f"(c[0]), "+f"(c[1]), "+f"(c[2]), "+f"(c[3])
        : "r"(a[0]), "r"(a[1]), "r"(a[2]), "r"(a[3]), "r"(b0), "r"(b1));
}

// ---------------------------------------------------------------------------
// Single fused kernel.
// Phase 0: CTA (mtile, ks) preps its 1/16 slice of ks's k-range of U_emb^T,
//          then a per-ks 16-CTA sense-reversal barrier (proven in R13).
// Phase 1: GEMM mainloop (unchanged), epilogue to exclusive partial slab.
// Phase 2: per-mtile LAST-ARRIVER ticket: the 18th CTA of each mtile
//          finalizes that mtile's teams. No spin, no residency assumption.
// ---------------------------------------------------------------------------
extern __shared__ __align__(16) char dynsmem[];

__global__ __launch_bounds__(256, 2) void gemm_kernel(
        const int* __restrict__ mask, const int* __restrict__ Uw,
        const float* __restrict__ e0, const float* __restrict__ e1,
        const float* __restrict__ e2, const float* __restrict__ e3,
        const float* __restrict__ e4, const float* __restrict__ e5,
        const float* __restrict__ Ts, float* __restrict__ out) {
    // layout: A0 [0,16K) A1 [16K,32K) B0 [32K,40K) B1 [40K,48K)
    const int tid  = threadIdx.x;
    const int lane = tid & 31;
    const int wid  = tid >> 5;
    const int wm   = wid & 3;    // 4 warps over M
    const int wn   = wid >> 2;   // 2 warps over N
    const int mtile  = blockIdx.x;
    const int ks     = blockIdx.y;
    const int mbase  = mtile * MT;
    const int ktile0 = ks * 43 + min(ks, 8);
    const int cnt    = 43 + (ks < 8 ? 1 : 0);

    // ---------------- Phase 0: prep this CTA's slice of B ----------------
    const bool is64 =
        (__syncthreads_and((tid < 64) ? (Uw[2 * tid + 1] == 0) : 1) != 0);

    const int nu     = cnt * 4;                   // users per CTA (172 or 176)
    const int kstart = ktile0 * 64 + mtile * nu;  // exclusive slice
    if (tid < nu) {
        const int k = kstart + tid;
        const int sizes[6] = {222, 27, 373, 283, 26, 7};
        const float* tabs[6] = {e0, e1, e2, e3, e4, e5};
        float v[36];
#pragma unroll
        for (int i = 0; i < 36; i++) v[i] = 0.0f;
        if (k < UN) {
            int idxs[6];
#pragma unroll
            for (int f = 0; f < 6; f++) {
                int elem = k * 6 + f;
                int idx = is64 ? Uw[2 * elem] : Uw[elem];
                idxs[f] = max(0, min(sizes[f] - 1, idx));
            }
#pragma unroll
            for (int f = 0; f < 6; f++) {
                const float* t = tabs[f] + (size_t)idxs[f] * 6;
#pragma unroll
                for (int d = 0; d < 6; d++) v[f * 6 + d] = t[d];
            }
        }
#pragma unroll
        for (int n = 0; n < 36; n++)
            g_ubT[(size_t)n * UN_PAD + k] = __float2half(v[n]);
        g_ubT[(size_t)36 * UN_PAD + k] = __float2half(1.0f);   // counts row
#pragma unroll
        for (int n = 37; n < 40; n++)
            g_ubT[(size_t)n * UN_PAD + k] = __float2half(0.0f);
    }
    __threadfence();       // publish B slice
    __syncthreads();
    if (tid == 0) {
        int s = *(volatile int*)&g_ks_sense[ks];
        int v = atomicAdd(&g_ks_count[ks], 1);
        if (v == 15) {
            g_ks_count[ks] = 0;
            __threadfence();
            atomicExch(&g_ks_sense[ks], s ^ 1);   // release
        } else {
            while (*(volatile int*)&g_ks_sense[ks] == s) __nanosleep(32);
        }
        __threadfence();   // acquire peers' slices
    }
    __syncthreads();

    // ---------------- Phase 1: GEMM (identical to R13) ----------------
    const uint32_t smem_u = cvta_sh(dynsmem);
    const uint32_t shA_u[2] = {smem_u, smem_u + 16384};
    const uint32_t shB_u[2] = {smem_u + 32768, smem_u + 40960};

    if (tid < 128) {   // zero B rows 40..47 in both buffers once
        int b = tid >> 6, off = (tid & 63) * 16;
        uint32_t a = shB_u[b] + 5120 + off;
        asm volatile("st.shared.v4.b32 [%0], {%1,%1,%1,%1};" :: "r"(a), "r"(0u));
    }

    int4 ra[8];
    int4 rb[2];

    auto load_regs = [&](int kt) {
        const int kb = (ktile0 + kt) * 64;
#pragma unroll
        for (int i = 0; i < 8; i++) {
            int slot = tid + i * 256;
            int row = slot >> 4, c4 = slot & 15;
            int gt = mbase + row, gk = kb + c4 * 4;
            if (gt < TN && gk < UN)
                ra[i] = __ldcs((const int4*)(mask + (size_t)gt * UN + gk));
            else
                ra[i] = make_int4(0, 0, 0, 0);
        }
        {
            int row = tid >> 3, c8 = tid & 7;
            rb[0] = *(const int4*)(const void*)(g_ubT + (size_t)row * UN_PAD + kb + c8 * 8);
        }
        if (tid < 64) {
            int slot = 256 + tid;
            int row = slot >> 3, c8 = slot & 7;
            rb[1] = *(const int4*)(const void*)(g_ubT + (size_t)row * UN_PAD + kb + c8 * 8);
        }
    };

    auto sts_tiles = [&](int buf) {
#pragma unroll
        for (int i = 0; i < 8; i++) {
            int slot = tid + i * 256;
            int row = slot >> 4, c4 = slot & 15;
            uint32_t p0 = (uint32_t)ra[i].x * 0x3C00u + (uint32_t)ra[i].y * 0x3C000000u;
            uint32_t p1 = (uint32_t)ra[i].z * 0x3C00u + (uint32_t)ra[i].w * 0x3C000000u;
            uint32_t a = shA_u[buf] + sw128(row * 128 + c4 * 8);
            asm volatile("st.shared.v2.b32 [%0], {%1,%2};" :: "r"(a), "r"(p0), "r"(p1));
        }
        {
            int row = tid >> 3, c8 = tid & 7;
            uint32_t a = shB_u[buf] + sw128(row * 128 + c8 * 16);
            asm volatile("st.shared.v4.b32 [%0], {%1,%2,%3,%4};"
                         :: "r"(a), "r"(rb[0].x), "r"(rb[0].y), "r"(rb[0].z), "r"(rb[0].w));
        }
        if (tid < 64) {
            int slot = 256 + tid;
            int row = slot >> 3, c8 = slot & 7;
            uint32_t a = shB_u[buf] + sw128(row * 128 + c8 * 16);
            asm volatile("st.shared.v4.b32 [%0], {%1,%2,%3,%4};"
                         :: "r"(a), "r"(rb[1].x), "r"(rb[1].y), "r"(rb[1].z), "r"(rb[1].w));
        }
    };

    float acc[2][4][4];
#pragma unroll
    for (int a = 0; a < 2; a++)
#pragma unroll
        for (int b = 0; b < 4; b++)
#pragma unroll
            for (int c = 0; c < 4; c++) acc[a][b][c] = 0.0f;

    load_regs(0);
    sts_tiles(0);
    if (cnt > 1) load_regs(1);
    __syncthreads();

    for (int kt = 0; kt < cnt; kt++) {
        const int cur = kt & 1;
        if (kt + 1 < cnt) sts_tiles(cur ^ 1);
        if (kt + 2 < cnt) load_regs(kt + 2);

#pragma unroll
        for (int kk = 0; kk < 4; kk++) {
            const int kb2 = kk * 32;
            uint32_t A[2][4];
#pragma unroll
            for (int mi = 0; mi < 2; mi++) {
                int row = wm * 32 + mi * 16 + (lane & 15);
                ldsm_x4(A[mi], shA_u[cur] + sw128(row * 128 + kb2 + ((lane >> 4) << 4)));
            }
#pragma unroll
            for (int nj = 0; nj < 2; nj++) {
                if (wn == 1 && nj == 1) continue;   // cols 48..63 all-zero padding
                int nl = wn * 32 + nj * 16 + (lane & 7) + (((lane >> 4) & 1) << 3);
                uint32_t koff = kb2 + ((lane >> 3) & 1) * 16;
                uint32_t Bh[4];
                ldsm_x4(Bh, shB_u[cur] + sw128((uint32_t)nl * 128 + koff));
                mma16816(acc[0][nj * 2 + 0], A[0], Bh[0], Bh[1]);
                mma16816(acc[1][nj * 2 + 0], A[1], Bh[0], Bh[1]);
                mma16816(acc[0][nj * 2 + 1], A[0], Bh[2], Bh[3]);
                mma16816(acc[1][nj * 2 + 1], A[1], Bh[2], Bh[3]);
            }
        }
        __syncthreads();
    }

    // ---- epilogue: exclusive partial slab [gm][ks][40]; only cols < 40 ----
#pragma unroll
    for (int mi = 0; mi < 2; mi++)
#pragma unroll
        for (int nc = 0; nc < 4; nc++) {
            int gn = wn * 32 + nc * 8 + (lane & 3) * 2;
            if (gn >= 40) continue;
            int lm = wm * 32 + mi * 16 + (lane >> 2);
            int gm = mbase + lm;
            float* d0 = &g_partial[((size_t)gm * KSPLIT + ks) * 40 + gn];
            *(float2*)d0 = make_float2(acc[mi][nc][0], acc[mi][nc][1]);
            float* d1 = &g_partial[((size_t)(gm + 8) * KSPLIT + ks) * 40 + gn];
            *(float2*)d1 = make_float2(acc[mi][nc][2], acc[mi][nc][3]);
        }

    // ---------------- Phase 2: per-mtile last-arriver finalize ----------------
    __threadfence();       // publish this CTA's slab
    __syncthreads();
    __shared__ int s_last;
    if (tid == 0) {
        int ticket = atomicAdd(&g_m_count[mtile], 1);
        s_last = (ticket == KSPLIT - 1) ? 1 : 0;
    }
    __syncthreads();
    if (!s_last) return;
    __threadfence();       // acquire all 18 slabs of this mtile

    {
        __shared__ float sv[6][40];
        const int n  = tid % 40;
        const int tl = tid / 40;    // 0..6 (only tl<6 used)
        for (int tb = 0; tb < MT; tb += 6) {
            const int lrow = tb + tl;
            const int t = mbase + lrow;
            const bool act = (tid < 240) && (lrow < MT) && (t < TN);
            if (act) {
                float s = 0.0f;
#pragma unroll
                for (int ksp = 0; ksp < KSPLIT; ksp++)
                    s += g_partial[((size_t)t * KSPLIT + ksp) * 40 + n];
                sv[tl][n] = s;
            }
            __syncthreads();
            if (act && n < 36)
                out[(size_t)t * NOUT + TF + n] = sv[tl][n] / sv[tl][36];
            if (tid < 96) {   // statics: 6 teams x 16 cols
                int lr2 = tb + tid / 16, i = tid % 16;
                int tt = mbase + lr2;
                if (lr2 < MT && tt < TN)
                    out[(size_t)tt * NOUT + i] = Ts[(size_t)tt * TF + i];
            }
            __syncthreads();
        }
    }
    if (tid == 0) g_m_count[mtile] = 0;   // reset for next graph replay
}

// ---------------------------------------------------------------------------
// Inputs (metadata order): T_static f32[2000,16], U_static int (probed),
// team_user_matrix i32[2000,50000], emb0..emb5 f32. Output f32[2000,52].
// ---------------------------------------------------------------------------
extern "C" void kernel_launch(void* const* d_in, const int* in_sizes, int n_in,
                              void* d_out, int out_size) {
    const float* Ts   = (const float*)d_in[0];
    const int*   Uw   = (const int*)d_in[1];
    const int*   mask = (const int*)d_in[2];
    const float* e0 = (const float*)d_in[3];
    const float* e1 = (const float*)d_in[4];
    const float* e2 = (const float*)d_in[5];
    const float* e3 = (const float*)d_in[6];
    const float* e4 = (const float*)d_in[7];
    const float* e5 = (const float*)d_in[8];
    float* out = (float*)d_out;

    static bool attr_set = false;
    if (!attr_set) {
        cudaFuncSetAttribute(gemm_kernel, cudaFuncAttributeMaxDynamicSharedMemorySize, 49152);
        attr_set = true;
    }

    dim3 grid(MTILES, KSPLIT);
    gemm_kernel<<<grid, 256, 49152>>>(mask, Uw, e0, e1, e2, e3, e4, e5, Ts, out);
}